// round 17
// baseline (speedup 1.0000x reference)
#include <cuda_runtime.h>
#include <cstdint>

// Problem constants
#define BB   32
#define NN   512
#define EE   512
#define HH   8
#define DD   8
#define PP   64          // H*D
#define P3   192         // q|k|v concatenated
#define ROWS (BB*NN)     // 16384
#define LN_EPS 1e-5f
// 0.25 * log2(e)
#define CEXP 0.36067376022224085f

typedef unsigned long long u64;

// ---------------- device scratch (static; no allocation) ----------------
__device__ float g_mean[ROWS];
__device__ float g_rstd[ROWS];
__device__ float g_WT3[EE * P3];     // [e][p] folded+transposed weights (q|k|v)
__device__ float g_bias3[P3];        // folded biases
__device__ float g_Wl2[NN * PP];     // [n][p]
__device__ float g_c0p[64];          // c0 partials
__device__ float g_qkv[(size_t)ROWS * P3];  // [row][192] = q|k|v
__device__ float g_part[BB * HH * 2];       // per (b,h,half) partials

// ---------------- f32x2 helpers (packed fp32 pair ops) ----------------
__device__ __forceinline__ u64 f2fma(u64 a, u64 b, u64 c) {
    u64 d; asm("fma.rn.f32x2 %0,%1,%2,%3;" : "=l"(d) : "l"(a), "l"(b), "l"(c)); return d;
}
__device__ __forceinline__ u64 f2mul(u64 a, u64 b) {
    u64 d; asm("mul.rn.f32x2 %0,%1,%2;" : "=l"(d) : "l"(a), "l"(b)); return d;
}
__device__ __forceinline__ u64 f2add(u64 a, u64 b) {
    u64 d; asm("add.rn.f32x2 %0,%1,%2;" : "=l"(d) : "l"(a), "l"(b)); return d;
}
__device__ __forceinline__ u64 f2pack(float lo, float hi) {
    u64 d; asm("mov.b64 %0,{%1,%2};" : "=l"(d) : "f"(lo), "f"(hi)); return d;
}
__device__ __forceinline__ float f2sum(u64 a) {
    float lo, hi; asm("mov.b64 {%0,%1},%2;" : "=f"(lo), "=f"(hi) : "l"(a)); return lo + hi;
}
__device__ __forceinline__ void f2unpack(u64 a, float& lo, float& hi) {
    asm("mov.b64 {%0,%1},%2;" : "=f"(lo), "=f"(hi) : "l"(a));
}
__device__ __forceinline__ float fast_ex2(float t) {
    float w; asm("ex2.approx.f32 %0, %1;" : "=f"(w) : "f"(t)); return w;
}

// ---------------- fused prep: fold(192) | stats(2048) | wl2(512) ----------------
__global__ __launch_bounds__(256) void prep_k(
    const float* __restrict__ x,
    const float* __restrict__ gq, const float* __restrict__ bq_,
    const float* __restrict__ gk, const float* __restrict__ bk_,
    const float* __restrict__ gv, const float* __restrict__ bv_,
    const float* __restrict__ Wq, const float* __restrict__ bq,
    const float* __restrict__ Wk, const float* __restrict__ bk,
    const float* __restrict__ Wv, const float* __restrict__ bv,
    const float* __restrict__ Wo, const float* __restrict__ Wl) {
    __shared__ float sm[256];
    const int bi = blockIdx.x;
    const int tid = threadIdx.x;

    if (bi < 192) {
        // ---- fold LN affine into proj weights ----
        const int which = bi >> 6, p = bi & 63;
        const float* W    = which == 0 ? Wq  : which == 1 ? Wk  : Wv;
        const float* bias = which == 0 ? bq  : which == 1 ? bk  : bv;
        const float* g    = which == 0 ? gq  : which == 1 ? gk  : gv;
        const float* bln  = which == 0 ? bq_ : which == 1 ? bk_ : bv_;
        const int colOff = which * 64;
        float s = 0.f;
        for (int e = tid; e < EE; e += 256) {
            float w = W[p * EE + e];
            g_WT3[(size_t)e * 192 + colOff + p] = w * g[e];
            s += w * bln[e];
        }
#pragma unroll
        for (int o = 16; o; o >>= 1) s += __shfl_xor_sync(0xffffffffu, s, o);
        if ((tid & 31) == 0) sm[tid >> 5] = s;
        __syncthreads();
        if (tid == 0) {
            float t = 0.f;
#pragma unroll
            for (int i = 0; i < 8; i++) t += sm[i];
            g_bias3[colOff + p] = bias[p] + t;
        }
    } else if (bi < 2240) {
        // ---- LN row stats (8 rows per block) ----
        int row  = (bi - 192) * 8 + (tid >> 5);
        int lane = tid & 31;
        const float4* xr = (const float4*)(x + (size_t)row * EE);
        float s = 0.f, ss = 0.f;
#pragma unroll
        for (int i = 0; i < 4; i++) {
            float4 v = xr[i * 32 + lane];
            s  += v.x + v.y + v.z + v.w;
            ss += v.x * v.x + v.y * v.y + v.z * v.z + v.w * v.w;
        }
#pragma unroll
        for (int o = 16; o; o >>= 1) {
            s  += __shfl_xor_sync(0xffffffffu, s,  o);
            ss += __shfl_xor_sync(0xffffffffu, ss, o);
        }
        if (lane == 0) {
            float mean = s * (1.f / EE);
            float var  = ss * (1.f / EE) - mean * mean;
            g_mean[row] = mean;
            g_rstd[row] = rsqrtf(var + LN_EPS);
        }
    } else {
        // ---- Wl2[n][p] = sum_e Wo[e][p] * Wl[n*E+e] ----
        const int n = bi - 2240;
        const int p = tid & 63;
        const int q = tid >> 6;                 // 0..3
        const float* wr = Wl + (size_t)n * EE;
        float s = 0.f;
#pragma unroll 4
        for (int e = q * 128; e < (q + 1) * 128; e++)
            s += Wo[e * PP + p] * wr[e];
        sm[q * 64 + p] = s;
        __syncthreads();
        if (q == 0)
            g_Wl2[n * PP + p] = (sm[p] + sm[64 + p]) + (sm[128 + p] + sm[192 + p]);
    }
}

// ---------------- c0 partials (standalone; keeps attn in ncu capture slot 4) ----------------
__global__ __launch_bounds__(256) void c0p_k(const float* __restrict__ bo,
                                             const float* __restrict__ Wl) {
    __shared__ float red[8];
    const int tid = threadIdx.x;
    const int base = blockIdx.x * (NN * EE / 64);   // 4096 elems per block
    float s = 0.f;
#pragma unroll 4
    for (int k = 0; k < 4096; k += 256) {
        int idx = base + k + tid;
        s += bo[idx & (EE - 1)] * Wl[idx];
    }
#pragma unroll
    for (int o = 16; o; o >>= 1) s += __shfl_xor_sync(0xffffffffu, s, o);
    if ((tid & 31) == 0) red[tid >> 5] = s;
    __syncthreads();
    if (tid == 0) {
        float t = 0.f;
#pragma unroll
        for (int i = 0; i < 8; i++) t += red[i];
        g_c0p[blockIdx.x] = t;
    }
}

// ---------------- fused LN-apply + QKV projection GEMM ----------------
// out[row][0:192] = xn[row] @ WT3 + bias3 ; M=16384 N=192 K=512
// tile 128x64, BK=16, 256 threads, 8x4 register blocking, f32x2 accumulation.
__global__ __launch_bounds__(256) void proj_gemm(const float* __restrict__ x) {
    const int nb = blockIdx.x;     // 0..2
    const int mb = blockIdx.y;     // 0..127
    __shared__ __align__(16) float As[16][132];
    __shared__ __align__(16) float Bs[16][64];
    const int t  = threadIdx.x;
    const int tx = t & 15, ty = t >> 4;
    const int am = t >> 2;              // 0..63
    const int ac = (t & 3) << 2;        // 0,4,8,12
    const int row0 = mb * 128;
    const int rA0 = row0 + am, rA1 = row0 + am + 64;
    const float mean0 = g_mean[rA0], rstd0 = g_rstd[rA0];
    const float mean1 = g_mean[rA1], rstd1 = g_rstd[rA1];
    const int bk = t >> 4;              // 0..15
    const int bn = (t & 15) << 2;

    u64 acc2[4][4];
#pragma unroll
    for (int i = 0; i < 4; i++)
#pragma unroll
        for (int j = 0; j < 4; j++) acc2[i][j] = 0ull;

    for (int kk = 0; kk < EE; kk += 16) {
        float4 a0 = *(const float4*)&x[(size_t)rA0 * EE + kk + ac];
        float4 a1 = *(const float4*)&x[(size_t)rA1 * EE + kk + ac];
        float4 bv = *(const float4*)&g_WT3[(size_t)(kk + bk) * P3 + nb * 64 + bn];
        As[ac + 0][am] = (a0.x - mean0) * rstd0;
        As[ac + 1][am] = (a0.y - mean0) * rstd0;
        As[ac + 2][am] = (a0.z - mean0) * rstd0;
        As[ac + 3][am] = (a0.w - mean0) * rstd0;
        As[ac + 0][am + 64] = (a1.x - mean1) * rstd1;
        As[ac + 1][am + 64] = (a1.y - mean1) * rstd1;
        As[ac + 2][am + 64] = (a1.z - mean1) * rstd1;
        As[ac + 3][am + 64] = (a1.w - mean1) * rstd1;
        *(float4*)&Bs[bk][bn] = bv;
        __syncthreads();
#pragma unroll
        for (int k = 0; k < 16; k++) {
            float a[8], b[4];
            *(float4*)&a[0] = *(const float4*)&As[k][ty * 8];
            *(float4*)&a[4] = *(const float4*)&As[k][ty * 8 + 4];
            *(float4*)&b[0] = *(const float4*)&Bs[k][tx * 4];
            u64 aP[4];
#pragma unroll
            for (int i = 0; i < 4; i++) aP[i] = f2pack(a[2 * i], a[2 * i + 1]);
            u64 bD[4];
#pragma unroll
            for (int j = 0; j < 4; j++) bD[j] = f2pack(b[j], b[j]);
#pragma unroll
            for (int i = 0; i < 4; i++)
#pragma unroll
                for (int j = 0; j < 4; j++) acc2[i][j] = f2fma(aP[i], bD[j], acc2[i][j]);
        }
        __syncthreads();
    }
    const float4 bias = *(const float4*)&g_bias3[nb * 64 + tx * 4];
#pragma unroll
    for (int ip = 0; ip < 4; ip++) {
        float4 o0, o1;
        float lo, hi;
        f2unpack(acc2[ip][0], lo, hi); o0.x = lo + bias.x; o1.x = hi + bias.x;
        f2unpack(acc2[ip][1], lo, hi); o0.y = lo + bias.y; o1.y = hi + bias.y;
        f2unpack(acc2[ip][2], lo, hi); o0.z = lo + bias.z; o1.z = hi + bias.z;
        f2unpack(acc2[ip][3], lo, hi); o0.w = lo + bias.w; o1.w = hi + bias.w;
        *(float4*)&g_qkv[(size_t)(row0 + ty * 8 + 2 * ip) * P3 + nb * 64 + tx * 4] = o0;
        *(float4*)&g_qkv[(size_t)(row0 + ty * 8 + 2 * ip + 1) * P3 + nb * 64 + tx * 4] = o1;
    }
}

// ---------------- Hopfield attention: thread handles TWO query rows ----------------
// grid (B*H, 2), block 128: rows i0 = y*256+tid and i1 = i0+128.
// ncu R15: LDS pipe 65.6% was the binder (fma 56%). Each kt/vt LDS.128 now feeds
// 2 scores + 2 accumulations (4 uses vs 2) -> LDS instruction count halves.
// j stays warp-uniform (broadcast LDS) — load-bearing, do not break.
__global__ __launch_bounds__(128) void attn_k() {
    __shared__ __align__(16) u64 kt[NN / 2][8];
    __shared__ __align__(16) u64 vt[NN / 2][8];
    __shared__ float red[4];
    const int bh = blockIdx.x;
    const int b = bh >> 3, h = bh & 7;
    const int tid = threadIdx.x;
    const int i0 = blockIdx.y * 256 + tid;
    const int i1 = i0 + 128;

    // cooperative k/v load into pair-interleaved smem (512 rows / 128 threads)
    float* ktf = (float*)kt;
    float* vtf = (float*)vt;
    for (int r = tid; r < NN; r += 128) {
        const float* src = g_qkv + (size_t)(b * NN + r) * P3 + h * DD;
        float4 ka = *(const float4*)(src + 64);
        float4 kb = *(const float4*)(src + 68);
        float4 va = *(const float4*)(src + 128);
        float4 vb = *(const float4*)(src + 132);
        int base = (r >> 1) * 16 + (r & 1);
        ktf[base + 0]  = ka.x; ktf[base + 2]  = ka.y;
        ktf[base + 4]  = ka.z; ktf[base + 6]  = ka.w;
        ktf[base + 8]  = kb.x; ktf[base + 10] = kb.y;
        ktf[base + 12] = kb.z; ktf[base + 14] = kb.w;
        vtf[base + 0]  = va.x; vtf[base + 2]  = va.y;
        vtf[base + 4]  = va.z; vtf[base + 6]  = va.w;
        vtf[base + 8]  = vb.x; vtf[base + 10] = vb.y;
        vtf[base + 12] = vb.z; vtf[base + 14] = vb.w;
    }
    const float* qrA = g_qkv + (size_t)(b * NN + i0) * P3 + h * DD;
    const float* qrB = g_qkv + (size_t)(b * NN + i1) * P3 + h * DD;
    float4 qa0 = *(const float4*)qrA, qa1 = *(const float4*)(qrA + 4);
    float4 qb0 = *(const float4*)qrB, qb1 = *(const float4*)(qrB + 4);
    u64 xa[8], xb[8];
    xa[0] = f2pack(qa0.x * CEXP, qa0.x * CEXP);
    xa[1] = f2pack(qa0.y * CEXP, qa0.y * CEXP);
    xa[2] = f2pack(qa0.z * CEXP, qa0.z * CEXP);
    xa[3] = f2pack(qa0.w * CEXP, qa0.w * CEXP);
    xa[4] = f2pack(qa1.x * CEXP, qa1.x * CEXP);
    xa[5] = f2pack(qa1.y * CEXP, qa1.y * CEXP);
    xa[6] = f2pack(qa1.z * CEXP, qa1.z * CEXP);
    xa[7] = f2pack(qa1.w * CEXP, qa1.w * CEXP);
    xb[0] = f2pack(qb0.x * CEXP, qb0.x * CEXP);
    xb[1] = f2pack(qb0.y * CEXP, qb0.y * CEXP);
    xb[2] = f2pack(qb0.z * CEXP, qb0.z * CEXP);
    xb[3] = f2pack(qb0.w * CEXP, qb0.w * CEXP);
    xb[4] = f2pack(qb1.x * CEXP, qb1.x * CEXP);
    xb[5] = f2pack(qb1.y * CEXP, qb1.y * CEXP);
    xb[6] = f2pack(qb1.z * CEXP, qb1.z * CEXP);
    xb[7] = f2pack(qb1.w * CEXP, qb1.w * CEXP);
    __syncthreads();

    // 3 retrieval rounds over k (both rows share every kt load)
#pragma unroll 1
    for (int it = 0; it < 3; it++) {
        u64 aA[8], aB[8];
#pragma unroll
        for (int d = 0; d < 8; d++) { aA[d] = 0ull; aB[d] = 0ull; }
        u64 dnA = 0ull, dnB = 0ull;
#pragma unroll 2
        for (int jp = 0; jp < NN / 2; jp++) {
            const ulonglong2* kr = (const ulonglong2*)kt[jp];
            ulonglong2 p0 = kr[0], p1 = kr[1], p2 = kr[2], p3 = kr[3];
            u64 sA = f2mul(xa[0], p0.x);
            sA = f2fma(xa[1], p0.y, sA);
            sA = f2fma(xa[2], p1.x, sA);
            sA = f2fma(xa[3], p1.y, sA);
            sA = f2fma(xa[4], p2.x, sA);
            sA = f2fma(xa[5], p2.y, sA);
            sA = f2fma(xa[6], p3.x, sA);
            sA = f2fma(xa[7], p3.y, sA);
            u64 sB = f2mul(xb[0], p0.x);
            sB = f2fma(xb[1], p0.y, sB);
            sB = f2fma(xb[2], p1.x, sB);
            sB = f2fma(xb[3], p1.y, sB);
            sB = f2fma(xb[4], p2.x, sB);
            sB = f2fma(xb[5], p2.y, sB);
            sB = f2fma(xb[6], p3.x, sB);
            sB = f2fma(xb[7], p3.y, sB);
            float sa0, sa1, sb0, sb1;
            f2unpack(sA, sa0, sa1);
            f2unpack(sB, sb0, sb1);
            u64 wA = f2pack(fast_ex2(sa0), fast_ex2(sa1));
            u64 wB = f2pack(fast_ex2(sb0), fast_ex2(sb1));
            dnA = f2add(dnA, wA);
            dnB = f2add(dnB, wB);
            aA[0] = f2fma(wA, p0.x, aA[0]);  aB[0] = f2fma(wB, p0.x, aB[0]);
            aA[1] = f2fma(wA, p0.y, aA[1]);  aB[1] = f2fma(wB, p0.y, aB[1]);
            aA[2] = f2fma(wA, p1.x, aA[2]);  aB[2] = f2fma(wB, p1.x, aB[2]);
            aA[3] = f2fma(wA, p1.y, aA[3]);  aB[3] = f2fma(wB, p1.y, aB[3]);
            aA[4] = f2fma(wA, p2.x, aA[4]);  aB[4] = f2fma(wB, p2.x, aB[4]);
            aA[5] = f2fma(wA, p2.y, aA[5]);  aB[5] = f2fma(wB, p2.y, aB[5]);
            aA[6] = f2fma(wA, p3.x, aA[6]);  aB[6] = f2fma(wB, p3.x, aB[6]);
            aA[7] = f2fma(wA, p3.y, aA[7]);  aB[7] = f2fma(wB, p3.y, aB[7]);
        }
        float icA = CEXP / f2sum(dnA);
        float icB = CEXP / f2sum(dnB);
#pragma unroll
        for (int d = 0; d < 8; d++) {
            float t = f2sum(aA[d]) * icA; xa[d] = f2pack(t, t);
            float u = f2sum(aB[d]) * icB; xb[d] = f2pack(u, u);
        }
    }

    // final round: scores from k, accumulate v (shared loads for both rows)
    u64 aA[8], aB[8];
#pragma unroll
    for (int d = 0; d < 8; d++) { aA[d] = 0ull; aB[d] = 0ull; }
    u64 dnA = 0ull, dnB = 0ull;
#pragma unroll 2
    for (int jp = 0; jp < NN / 2; jp++) {
        const ulonglong2* kr = (const ulonglong2*)kt[jp];
        ulonglong2 p0 = kr[0], p1 = kr[1], p2 = kr[2], p3 = kr[3];
        u64 sA = f2mul(xa[0], p0.x);
        sA = f2fma(xa[1], p0.y, sA);
        sA = f2fma(xa[2], p1.x, sA);
        sA = f2fma(xa[3], p1.y, sA);
        sA = f2fma(xa[4], p2.x, sA);
        sA = f2fma(xa[5], p2.y, sA);
        sA = f2fma(xa[6], p3.x, sA);
        sA = f2fma(xa[7], p3.y, sA);
        u64 sB = f2mul(xb[0], p0.x);
        sB = f2fma(xb[1], p0.y, sB);
        sB = f2fma(xb[2], p1.x, sB);
        sB = f2fma(xb[3], p1.y, sB);
        sB = f2fma(xb[4], p2.x, sB);
        sB = f2fma(xb[5], p2.y, sB);
        sB = f2fma(xb[6], p3.x, sB);
        sB = f2fma(xb[7], p3.y, sB);
        float sa0, sa1, sb0, sb1;
        f2unpack(sA, sa0, sa1);
        f2unpack(sB, sb0, sb1);
        u64 wA = f2pack(fast_ex2(sa0), fast_ex2(sa1));
        u64 wB = f2pack(fast_ex2(sb0), fast_ex2(sb1));
        dnA = f2add(dnA, wA);
        dnB = f2add(dnB, wB);
        const ulonglong2* vr = (const ulonglong2*)vt[jp];
        ulonglong2 w0 = vr[0], w1 = vr[1], w2 = vr[2], w3 = vr[3];
        aA[0] = f2fma(wA, w0.x, aA[0]);  aB[0] = f2fma(wB, w0.x, aB[0]);
        aA[1] = f2fma(wA, w0.y, aA[1]);  aB[1] = f2fma(wB, w0.y, aB[1]);
        aA[2] = f2fma(wA, w1.x, aA[2]);  aB[2] = f2fma(wB, w1.x, aB[2]);
        aA[3] = f2fma(wA, w1.y, aA[3]);  aB[3] = f2fma(wB, w1.y, aB[3]);
        aA[4] = f2fma(wA, w2.x, aA[4]);  aB[4] = f2fma(wB, w2.x, aB[4]);
        aA[5] = f2fma(wA, w2.y, aA[5]);  aB[5] = f2fma(wB, w2.y, aB[5]);
        aA[6] = f2fma(wA, w3.x, aA[6]);  aB[6] = f2fma(wB, w3.x, aB[6]);
        aA[7] = f2fma(wA, w3.y, aA[7]);  aB[7] = f2fma(wB, w3.y, aB[7]);
    }
    float invA = 1.0f / f2sum(dnA);
    float invB = 1.0f / f2sum(dnB);

    // classifier contributions for both rows
    const float4* wlA = (const float4*)(g_Wl2 + i0 * PP + h * DD);
    const float4* wlB = (const float4*)(g_Wl2 + i1 * PP + h * DD);
    float4 wA0 = wlA[0], wA1 = wlA[1];
    float4 wB0 = wlB[0], wB1 = wlB[1];
    u64 tA = f2mul(aA[0], f2pack(wA0.x, wA0.x));
    tA = f2fma(aA[1], f2pack(wA0.y, wA0.y), tA);
    tA = f2fma(aA[2], f2pack(wA0.z, wA0.z), tA);
    tA = f2fma(aA[3], f2pack(wA0.w, wA0.w), tA);
    tA = f2fma(aA[4], f2pack(wA1.x, wA1.x), tA);
    tA = f2fma(aA[5], f2pack(wA1.y, wA1.y), tA);
    tA = f2fma(aA[6], f2pack(wA1.z, wA1.z), tA);
    tA = f2fma(aA[7], f2pack(wA1.w, wA1.w), tA);
    u64 tB = f2mul(aB[0], f2pack(wB0.x, wB0.x));
    tB = f2fma(aB[1], f2pack(wB0.y, wB0.y), tB);
    tB = f2fma(aB[2], f2pack(wB0.z, wB0.z), tB);
    tB = f2fma(aB[3], f2pack(wB0.w, wB0.w), tB);
    tB = f2fma(aB[4], f2pack(wB1.x, wB1.x), tB);
    tB = f2fma(aB[5], f2pack(wB1.y, wB1.y), tB);
    tB = f2fma(aB[6], f2pack(wB1.z, wB1.z), tB);
    tB = f2fma(aB[7], f2pack(wB1.w, wB1.w), tB);
    float p = f2sum(tA) * invA + f2sum(tB) * invB;

#pragma unroll
    for (int o = 16; o; o >>= 1) p += __shfl_xor_sync(0xffffffffu, p, o);
    if ((tid & 31) == 0) red[tid >> 5] = p;
    __syncthreads();
    if (tid == 0)
        g_part[blockIdx.x * 2 + blockIdx.y] = red[0] + red[1] + red[2] + red[3];
}

// ---------------- final per-batch reduction (+ c0 merge), parallel ----------------
// one 1024-thread block: warp w handles batch b=w; 16 attn partials per batch
// plus 64 c0 partials folded into one shfl reduction.
__global__ __launch_bounds__(1024) void finish_k(const float* __restrict__ bl,
                                                 float* __restrict__ y) {
    const int b = threadIdx.x >> 5;
    const int lane = threadIdx.x & 31;
    float s = g_c0p[lane] + g_c0p[lane + 32];
    if (lane < 16) s += g_part[b * 16 + lane];
#pragma unroll
    for (int o = 16; o; o >>= 1) s += __shfl_xor_sync(0xffffffffu, s, o);
    if (lane == 0) y[b] = s + bl[0];
}

// ---------------- launch ----------------
// attn_k stays the 4th launch (ncu's bounded capture lands on launch #4).
extern "C" void kernel_launch(void* const* d_in, const int* in_sizes, int n_in,
                              void* d_out, int out_size) {
    const float* x   = (const float*)d_in[0];
    const float* gq  = (const float*)d_in[1];
    const float* bq_ = (const float*)d_in[2];
    const float* gk  = (const float*)d_in[3];
    const float* bk_ = (const float*)d_in[4];
    const float* gv  = (const float*)d_in[5];
    const float* bv_ = (const float*)d_in[6];
    const float* Wq  = (const float*)d_in[7];
    const float* bq  = (const float*)d_in[8];
    const float* Wk  = (const float*)d_in[9];
    const float* bk  = (const float*)d_in[10];
    const float* Wv  = (const float*)d_in[11];
    const float* bv  = (const float*)d_in[12];
    const float* Wo  = (const float*)d_in[13];
    const float* bo  = (const float*)d_in[14];
    const float* Wl  = (const float*)d_in[15];
    const float* bl  = (const float*)d_in[16];
    float* y = (float*)d_out;

    prep_k<<<2752, 256>>>(x, gq, bq_, gk, bk_, gv, bv_,
                          Wq, bq, Wk, bk, Wv, bv, Wo, Wl);       // 1
    proj_gemm<<<dim3(3, 128), 256>>>(x);                          // 2
    c0p_k<<<64, 256>>>(bo, Wl);                                   // 3
    attn_k<<<dim3(BB * HH, 2), 128>>>();                          // 4  <- ncu capture slot
    finish_k<<<1, 1024>>>(bl, y);                                 // 5
}